// round 14
// baseline (speedup 1.0000x reference)
#include <cuda_runtime.h>
#include <cuda_fp16.h>

// ---------------------------------------------------------------------------
// HMPNN layer, R12:
//  - prep U-build: 2 nodes packed in f32x2 (FFMA2), o-half lane split,
//    lane-duplicated SMEM weights -> halved issue count, ~70 regs.
//  - edge: ea row fetched with one LDG.64 per lane + shfl redistribution
//    (saves ~1.5 L1 wavefronts/edge).
//   U[n,f,o] = sum_i x_src[n,i] * w_msg[f,i,o]   (f=16 block = xj@b_msg)
//   msg[e,o] = U[src,16,o] + sum_f ea[e,f] * U[src,f,o]
//   agg[n]   = segment_sum(msg) + x_indivi @ root + bias
//   out      = sigmoid( concat(sig(agg_a), sig(agg_b)) @ w_lin + b_lin )
// ---------------------------------------------------------------------------

#define NMAX 50000
#define UROWP 320            // padded row: 320 halves = 640B = 5 x 128B lines

typedef unsigned long long ull;

__device__ float  g_agg[2][NMAX * 16];
__device__ __align__(128) __half g_U[2][NMAX * UROWP];

__device__ __forceinline__ ull pk2(float x, float y) {
    ull r;
    asm("mov.b64 %0, {%1,%2};" : "=l"(r)
        : "r"(__float_as_uint(x)), "r"(__float_as_uint(y)));
    return r;
}
__device__ __forceinline__ void unpk2(ull a, float& x, float& y) {
    unsigned lo, hi;
    asm("mov.b64 {%0,%1}, %2;" : "=r"(lo), "=r"(hi) : "l"(a));
    x = __uint_as_float(lo);
    y = __uint_as_float(hi);
}
__device__ __forceinline__ ull fma2(ull a, ull b, ull c) {
    ull r;
    asm("fma.rn.f32x2 %0, %1, %2, %3;" : "=l"(r) : "l"(a), "l"(b), "l"(c));
    return r;
}
__device__ __forceinline__ void red4(float* p, float a, float b, float c, float d) {
    asm volatile("red.global.add.v4.f32 [%0], {%1,%2,%3,%4};"
                 :: "l"(p), "f"(a), "f"(b), "f"(c), "f"(d) : "memory");
}
__device__ __forceinline__ float sigmoidf(float x) {
    return 1.0f / (1.0f + __expf(-x));
}

// ---------------------------------------------------------------------------
// prep: grid.y roles.
//  role 0: init — 2 threads/node (lane = step): agg = bias + x_indivi@root
//  role 1: U_a  — thread = (node-pair, o-half); 2 nodes packed f32x2
//  role 2: U_b
// ---------------------------------------------------------------------------
__global__ __launch_bounds__(256) void prep_kernel(
    const float* __restrict__ x_indivi,
    const float* __restrict__ xs_a, const float* __restrict__ xs_b,
    const float* __restrict__ root_a, const float* __restrict__ bias_a,
    const float* __restrict__ root_b, const float* __restrict__ bias_b,
    const float* __restrict__ wm_a, const float* __restrict__ bm_a,
    const float* __restrict__ wm_b, const float* __restrict__ bm_b,
    int N, int nblk_u) {
    const int role = blockIdx.y;

    if (role == 0) {
        int t = blockIdx.x * 256 + threadIdx.x;
        int n = t >> 1;
        int l = t & 1;
        if (n >= N) return;
        const float* __restrict__ root = l ? root_b : root_a;
        const float* __restrict__ bias = l ? bias_b : bias_a;

        float x[16];
        const float4* xr = (const float4*)(x_indivi + n * 16);
#pragma unroll
        for (int j = 0; j < 4; ++j) {
            float4 v = xr[j];
            x[4 * j + 0] = v.x; x[4 * j + 1] = v.y;
            x[4 * j + 2] = v.z; x[4 * j + 3] = v.w;
        }
        float s[16];
#pragma unroll
        for (int o = 0; o < 16; ++o) s[o] = __ldg(bias + o);
#pragma unroll
        for (int i = 0; i < 16; ++i) {
            float xi = x[i];
            const float4* rr = (const float4*)(root + i * 16);
#pragma unroll
            for (int j = 0; j < 4; ++j) {
                float4 w = __ldg(rr + j);
                s[4 * j + 0] += xi * w.x;
                s[4 * j + 1] += xi * w.y;
                s[4 * j + 2] += xi * w.z;
                s[4 * j + 3] += xi * w.w;
            }
        }
        float4* dst = (float4*)(&g_agg[l][n * 16]);
#pragma unroll
        for (int j = 0; j < 4; ++j)
            dst[j] = make_float4(s[4 * j], s[4 * j + 1], s[4 * j + 2], s[4 * j + 3]);
        return;
    }

    // roles 1,2: U table build (f32x2, 2 nodes/thread, o-half lanes)
    if (blockIdx.x >= nblk_u) return;    // uniform per block

    const float* __restrict__ xs = (role == 1) ? xs_a : xs_b;
    const float* __restrict__ wm = (role == 1) ? wm_a : wm_b;
    const float* __restrict__ bm = (role == 1) ? bm_a : bm_b;
    __half* __restrict__ U = g_U[role - 1];

    __shared__ __align__(16) ull W2[17 * 256];   // [f][i][o], lanes duplicated
    for (int k = threadIdx.x; k < 4096; k += 256) {
        float v = wm[k];
        W2[k] = pk2(v, v);
    }
    if (threadIdx.x < 256) {
        float v = bm[threadIdx.x];
        W2[4096 + threadIdx.x] = pk2(v, v);
    }
    __syncthreads();

    int idx = blockIdx.x * 256 + threadIdx.x;
    int p = idx >> 1;               // node pair
    int l = idx & 1;                // o-half
    int n0 = 2 * p;
    if (n0 >= N) return;
    int n1 = min(n0 + 1, N - 1);
    bool two = (n0 + 1 < N);

    ull xj[16];
    {
        const float4* x0 = (const float4*)(xs + n0 * 16);
        const float4* x1 = (const float4*)(xs + n1 * 16);
#pragma unroll
        for (int j = 0; j < 4; ++j) {
            float4 a = x0[j], b = x1[j];
            xj[4 * j + 0] = pk2(a.x, b.x);
            xj[4 * j + 1] = pk2(a.y, b.y);
            xj[4 * j + 2] = pk2(a.z, b.z);
            xj[4 * j + 3] = pk2(a.w, b.w);
        }
    }

    __half* U0 = U + (long)n0 * UROWP + l * 8;
    __half* U1 = U + (long)n1 * UROWP + l * 8;

#pragma unroll 1
    for (int f = 0; f < 17; ++f) {
        const ulonglong2* Wf = (const ulonglong2*)(W2 + f * 256 + l * 8);
        ull acc[8];
#pragma unroll
        for (int k = 0; k < 8; ++k) acc[k] = 0;
#pragma unroll
        for (int i = 0; i < 16; ++i) {
            ull xi = xj[i];
            const ulonglong2* wr = Wf + i * 8;   // 16 ull stride per i
#pragma unroll
            for (int k = 0; k < 4; ++k) {
                ulonglong2 w = wr[k];
                acc[2 * k + 0] = fma2(xi, w.x, acc[2 * k + 0]);
                acc[2 * k + 1] = fma2(xi, w.y, acc[2 * k + 1]);
            }
        }
        float a0[8], a1[8];
#pragma unroll
        for (int k = 0; k < 8; ++k) unpk2(acc[k], a0[k], a1[k]);
        __half2 h0[4], h1[4];
#pragma unroll
        for (int j = 0; j < 4; ++j) {
            h0[j] = __floats2half2_rn(a0[2 * j], a0[2 * j + 1]);
            h1[j] = __floats2half2_rn(a1[2 * j], a1[2 * j + 1]);
        }
        *(uint4*)(U0 + f * 16) = *(const uint4*)&h0[0];
        if (two) *(uint4*)(U1 + f * 16) = *(const uint4*)&h1[0];
    }
}

// ---------------------------------------------------------------------------
// edge: blockIdx.y = step. 8 lanes per edge; round c: octet loads one full
// 128B line (f-blocks 4c..4c+3); lane j owns f=4c+(j>>1), o-half j&1.
// ea row fetched via one LDG.64/lane, redistributed by shfl.
// Bias block: lanes 0/1. Butterfly shfl_xor(2),(4) reduces; lanes 0/1 scatter.
// ---------------------------------------------------------------------------
__global__ __launch_bounds__(256) void edge_kernel(
    const int* __restrict__ ei_a, const int* __restrict__ ei_b,
    const float* __restrict__ eat_a, const float* __restrict__ eat_b,
    int E) {
    const int step = blockIdx.y;
    const int*   __restrict__ ei  = step ? ei_b  : ei_a;
    const float* __restrict__ eat = step ? eat_b : eat_a;
    const __half* __restrict__ U  = g_U[step];
    float* __restrict__ agg       = g_agg[step];

    int t = blockIdx.x * 256 + threadIdx.x;
    int g = t >> 3;                 // edge index
    int j = t & 7;                  // octet lane
    bool valid = (g < E);
    if (g >= E) g = E - 1;          // clamp; keep lanes converged for shfl

    int w = threadIdx.x & 31;
    int ob = w & 24;                // octet base within warp
    int h = j & 1;                  // o-half
    int fi = j >> 1;                // f offset within each 4-block

    int s = __ldg(ei + g);

    const uint4* __restrict__ Ur = (const uint4*)(U + (long)s * UROWP);
    const float* __restrict__ ear = eat + (long)g * 16;

    // cooperative ea fetch: lane j holds ea[2j], ea[2j+1]
    float2 eap = __ldg((const float2*)ear + j);
    // redistribute: eaf[c] = ea[4c+fi]; src lane = ob + 2c + (fi>>1), comp = fi&1
    float eaf[4];
    int comp = fi & 1;
    int sbase = ob + (fi >> 1);
#pragma unroll
    for (int c = 0; c < 4; ++c) {
        float lo = __shfl_sync(0xffffffffu, eap.x, sbase + 2 * c);
        float hi = __shfl_sync(0xffffffffu, eap.y, sbase + 2 * c);
        eaf[c] = comp ? hi : lo;
    }

    float acc[8];
    if (j < 2) {                    // bias block (f=16), once per o-half group
        uint4 u = __ldg(Ur + 32 + j);
        const __half2* hh = (const __half2*)&u;
#pragma unroll
        for (int k = 0; k < 4; ++k) {
            float2 f2 = __half22float2(hh[k]);
            acc[2 * k + 0] = f2.x;
            acc[2 * k + 1] = f2.y;
        }
    } else {
#pragma unroll
        for (int k = 0; k < 8; ++k) acc[k] = 0.0f;
    }

#pragma unroll
    for (int c = 0; c < 4; ++c) {
        uint4 u = __ldg(Ur + c * 8 + j);    // full 128B line per octet
        float er = eaf[c];
        const __half2* hh = (const __half2*)&u;
#pragma unroll
        for (int k = 0; k < 4; ++k) {
            float2 f2 = __half22float2(hh[k]);
            acc[2 * k + 0] += er * f2.x;
            acc[2 * k + 1] += er * f2.y;
        }
    }

#pragma unroll
    for (int k = 0; k < 8; ++k)
        acc[k] += __shfl_xor_sync(0xffffffffu, acc[k], 2);
#pragma unroll
    for (int k = 0; k < 8; ++k)
        acc[k] += __shfl_xor_sync(0xffffffffu, acc[k], 4);

    if (valid && j < 2) {
        int d = __ldg(ei + E + g);
        float* base = &agg[d * 16 + 8 * h];
        red4(base,     acc[0], acc[1], acc[2], acc[3]);
        red4(base + 4, acc[4], acc[5], acc[6], acc[7]);
    }
}

// ---------------------------------------------------------------------------
// final: 2 lanes per node; lane l computes outputs 16l..16l+15
// ---------------------------------------------------------------------------
__global__ __launch_bounds__(256) void final_kernel(
    const float* __restrict__ w_lin,
    const float* __restrict__ b_lin,
    float* __restrict__ out, int N) {
    __shared__ __align__(16) float wl[32 * 32];
    __shared__ float bl[32];
    for (int k = threadIdx.x; k < 1024; k += 256) wl[k] = w_lin[k];
    if (threadIdx.x < 32) bl[threadIdx.x] = b_lin[threadIdx.x];
    __syncthreads();

    int t = blockIdx.x * 256 + threadIdx.x;
    int n = t >> 1;
    int l = t & 1;
    if (n >= N) return;

    float s[32];
    {
        const float4* ga = (const float4*)(&g_agg[0][n * 16]);
        const float4* gb = (const float4*)(&g_agg[1][n * 16]);
#pragma unroll
        for (int j = 0; j < 4; ++j) {
            float4 va = ga[j];
            s[4 * j + 0] = sigmoidf(va.x); s[4 * j + 1] = sigmoidf(va.y);
            s[4 * j + 2] = sigmoidf(va.z); s[4 * j + 3] = sigmoidf(va.w);
        }
#pragma unroll
        for (int j = 0; j < 4; ++j) {
            float4 vb = gb[j];
            s[16 + 4 * j + 0] = sigmoidf(vb.x); s[16 + 4 * j + 1] = sigmoidf(vb.y);
            s[16 + 4 * j + 2] = sigmoidf(vb.z); s[16 + 4 * j + 3] = sigmoidf(vb.w);
        }
    }

    float4 acc[4];
#pragma unroll
    for (int j = 0; j < 4; ++j) {
        int o = 16 * l + 4 * j;
        acc[j] = make_float4(bl[o], bl[o + 1], bl[o + 2], bl[o + 3]);
    }
#pragma unroll
    for (int k = 0; k < 32; ++k) {
        float sk = s[k];
        const float4* w4 = (const float4*)(wl + k * 32 + 16 * l);
#pragma unroll
        for (int j = 0; j < 4; ++j) {
            float4 w = w4[j];
            acc[j].x += sk * w.x;
            acc[j].y += sk * w.y;
            acc[j].z += sk * w.z;
            acc[j].w += sk * w.w;
        }
    }

    float4* o4 = (float4*)(out + n * 32 + 16 * l);
#pragma unroll
    for (int j = 0; j < 4; ++j)
        o4[j] = make_float4(sigmoidf(acc[j].x), sigmoidf(acc[j].y),
                            sigmoidf(acc[j].z), sigmoidf(acc[j].w));
}

// ---------------------------------------------------------------------------
extern "C" void kernel_launch(void* const* d_in, const int* in_sizes, int n_in,
                              void* d_out, int out_size) {
    const float* x_indivi = (const float*)d_in[0];
    const float* x_src_a  = (const float*)d_in[1];
    const float* x_src_b  = (const float*)d_in[2];
    const int*   ei_a     = (const int*)d_in[3];
    const int*   ei_b     = (const int*)d_in[4];
    const float* ea_a     = (const float*)d_in[5];
    const float* ea_b     = (const float*)d_in[6];
    const float* wm_a     = (const float*)d_in[7];
    const float* bm_a     = (const float*)d_in[8];
    const float* root_a   = (const float*)d_in[9];
    const float* bias_a   = (const float*)d_in[10];
    const float* wm_b     = (const float*)d_in[11];
    const float* bm_b     = (const float*)d_in[12];
    const float* root_b   = (const float*)d_in[13];
    const float* bias_b   = (const float*)d_in[14];
    const float* w_lin    = (const float*)d_in[15];
    const float* b_lin    = (const float*)d_in[16];
    float* out = (float*)d_out;

    int N = in_sizes[0] / 16;
    int E = in_sizes[3] / 2;   // edge_index is [2, E]

    int nb2 = (2 * N + 255) / 256;                 // role 0 blocks
    int nblk_u = (N + 255) / 256;                  // roles 1/2 blocks (N threads)
    int eb8 = (int)(((long)8 * E + 255) / 256);

    // launch 1: prep (init + both U tables)
    prep_kernel<<<dim3(nb2, 3), 256>>>(x_indivi, x_src_a, x_src_b,
                                       root_a, bias_a, root_b, bias_b,
                                       wm_a, bm_a, wm_b, bm_b, N, nblk_u);
    // launch 2: both edge steps
    edge_kernel<<<dim3(eb8, 2), 256>>>(ei_a, ei_b, ea_a, ea_b, E);
    // launch 3: final
    final_kernel<<<nb2, 256>>>(w_lin, b_lin, out, N);
}

// round 16
// speedup vs baseline: 1.0410x; 1.0410x over previous
#include <cuda_runtime.h>
#include <cuda_fp16.h>

// ---------------------------------------------------------------------------
// HMPNN layer, R14:
//  - prep U-build: scalar fp32, 2 nodes/thread, o-half lane split
//    (8 MAC per LDS.128, ~64 regs -> good occupancy; the measured sweet spot)
//  - edge: 8 lanes/edge, 128B-line gather, ea via LDG.64 + shfl redistribution
//   U[n,f,o] = sum_i x_src[n,i] * w_msg[f,i,o]   (f=16 block = xj@b_msg)
//   msg[e,o] = U[src,16,o] + sum_f ea[e,f] * U[src,f,o]
//   agg[n]   = segment_sum(msg) + x_indivi @ root + bias
//   out      = sigmoid( concat(sig(agg_a), sig(agg_b)) @ w_lin + b_lin )
// ---------------------------------------------------------------------------

#define NMAX 50000
#define UROWP 320            // padded row: 320 halves = 640B = 5 x 128B lines

__device__ float  g_agg[2][NMAX * 16];
__device__ __align__(128) __half g_U[2][NMAX * UROWP];

__device__ __forceinline__ void red4(float* p, float a, float b, float c, float d) {
    asm volatile("red.global.add.v4.f32 [%0], {%1,%2,%3,%4};"
                 :: "l"(p), "f"(a), "f"(b), "f"(c), "f"(d) : "memory");
}
__device__ __forceinline__ float sigmoidf(float x) {
    return 1.0f / (1.0f + __expf(-x));
}

// ---------------------------------------------------------------------------
// prep: grid.y roles.
//  role 0: init — 2 threads/node (lane = step): agg = bias + x_indivi@root
//  role 1: U_a  — thread = (node-pair, o-half); scalar fp32, 2 nodes/thread
//  role 2: U_b
// ---------------------------------------------------------------------------
__global__ __launch_bounds__(256) void prep_kernel(
    const float* __restrict__ x_indivi,
    const float* __restrict__ xs_a, const float* __restrict__ xs_b,
    const float* __restrict__ root_a, const float* __restrict__ bias_a,
    const float* __restrict__ root_b, const float* __restrict__ bias_b,
    const float* __restrict__ wm_a, const float* __restrict__ bm_a,
    const float* __restrict__ wm_b, const float* __restrict__ bm_b,
    int N, int nblk_u) {
    const int role = blockIdx.y;

    if (role == 0) {
        int t = blockIdx.x * 256 + threadIdx.x;
        int n = t >> 1;
        int l = t & 1;
        if (n >= N) return;
        const float* __restrict__ root = l ? root_b : root_a;
        const float* __restrict__ bias = l ? bias_b : bias_a;

        float x[16];
        const float4* xr = (const float4*)(x_indivi + n * 16);
#pragma unroll
        for (int j = 0; j < 4; ++j) {
            float4 v = xr[j];
            x[4 * j + 0] = v.x; x[4 * j + 1] = v.y;
            x[4 * j + 2] = v.z; x[4 * j + 3] = v.w;
        }
        float s[16];
#pragma unroll
        for (int o = 0; o < 16; ++o) s[o] = __ldg(bias + o);
#pragma unroll
        for (int i = 0; i < 16; ++i) {
            float xi = x[i];
            const float4* rr = (const float4*)(root + i * 16);
#pragma unroll
            for (int j = 0; j < 4; ++j) {
                float4 w = __ldg(rr + j);
                s[4 * j + 0] += xi * w.x;
                s[4 * j + 1] += xi * w.y;
                s[4 * j + 2] += xi * w.z;
                s[4 * j + 3] += xi * w.w;
            }
        }
        float4* dst = (float4*)(&g_agg[l][n * 16]);
#pragma unroll
        for (int j = 0; j < 4; ++j)
            dst[j] = make_float4(s[4 * j], s[4 * j + 1], s[4 * j + 2], s[4 * j + 3]);
        return;
    }

    // roles 1,2: U table build (scalar, 2 nodes/thread, o-half lanes)
    if (blockIdx.x >= nblk_u) return;    // uniform per block

    const float* __restrict__ xs = (role == 1) ? xs_a : xs_b;
    const float* __restrict__ wm = (role == 1) ? wm_a : wm_b;
    const float* __restrict__ bm = (role == 1) ? bm_a : bm_b;
    __half* __restrict__ U = g_U[role - 1];

    __shared__ __align__(16) float Ws[17 * 256];   // [f][i][o], f=16 = b_msg
    for (int k = threadIdx.x; k < 4096; k += 256) Ws[k] = wm[k];
    if (threadIdx.x < 256) Ws[4096 + threadIdx.x] = bm[threadIdx.x];
    __syncthreads();

    int idx = blockIdx.x * 256 + threadIdx.x;
    int p = idx >> 1;               // node pair
    int l = idx & 1;                // o-half
    int n0 = 2 * p;
    if (n0 >= N) return;
    int n1 = min(n0 + 1, N - 1);
    bool two = (n0 + 1 < N);

    float x0[16], x1[16];
    {
        const float4* xr0 = (const float4*)(xs + n0 * 16);
        const float4* xr1 = (const float4*)(xs + n1 * 16);
#pragma unroll
        for (int j = 0; j < 4; ++j) {
            float4 a = xr0[j], b = xr1[j];
            x0[4 * j + 0] = a.x; x0[4 * j + 1] = a.y;
            x0[4 * j + 2] = a.z; x0[4 * j + 3] = a.w;
            x1[4 * j + 0] = b.x; x1[4 * j + 1] = b.y;
            x1[4 * j + 2] = b.z; x1[4 * j + 3] = b.w;
        }
    }

    __half* U0 = U + (long)n0 * UROWP + l * 8;
    __half* U1 = U + (long)n1 * UROWP + l * 8;

#pragma unroll 1
    for (int f = 0; f < 17; ++f) {
        const float* Wf = Ws + f * 256 + l * 8;     // this lane's o-half
        float a0[8], a1[8];
#pragma unroll
        for (int o = 0; o < 8; ++o) { a0[o] = 0.0f; a1[o] = 0.0f; }
#pragma unroll
        for (int i = 0; i < 16; ++i) {
            const float4* wr = (const float4*)(Wf + i * 16);
            float4 w0 = wr[0];
            float4 w1 = wr[1];
            float xa = x0[i], xb = x1[i];
            a0[0] += xa * w0.x; a0[1] += xa * w0.y;
            a0[2] += xa * w0.z; a0[3] += xa * w0.w;
            a0[4] += xa * w1.x; a0[5] += xa * w1.y;
            a0[6] += xa * w1.z; a0[7] += xa * w1.w;
            a1[0] += xb * w0.x; a1[1] += xb * w0.y;
            a1[2] += xb * w0.z; a1[3] += xb * w0.w;
            a1[4] += xb * w1.x; a1[5] += xb * w1.y;
            a1[6] += xb * w1.z; a1[7] += xb * w1.w;
        }
        __half2 h0[4], h1[4];
#pragma unroll
        for (int j = 0; j < 4; ++j) {
            h0[j] = __floats2half2_rn(a0[2 * j], a0[2 * j + 1]);
            h1[j] = __floats2half2_rn(a1[2 * j], a1[2 * j + 1]);
        }
        *(uint4*)(U0 + f * 16) = *(const uint4*)&h0[0];
        if (two) *(uint4*)(U1 + f * 16) = *(const uint4*)&h1[0];
    }
}

// ---------------------------------------------------------------------------
// edge: blockIdx.y = step. 8 lanes per edge; round c: octet loads one full
// 128B line (f-blocks 4c..4c+3); lane j owns f=4c+(j>>1), o-half j&1.
// ea row fetched via one LDG.64/lane, redistributed by shfl.
// Bias block: lanes 0/1. Butterfly shfl_xor(2),(4) reduces; lanes 0/1 scatter.
// ---------------------------------------------------------------------------
__global__ __launch_bounds__(256) void edge_kernel(
    const int* __restrict__ ei_a, const int* __restrict__ ei_b,
    const float* __restrict__ eat_a, const float* __restrict__ eat_b,
    int E) {
    const int step = blockIdx.y;
    const int*   __restrict__ ei  = step ? ei_b  : ei_a;
    const float* __restrict__ eat = step ? eat_b : eat_a;
    const __half* __restrict__ U  = g_U[step];
    float* __restrict__ agg       = g_agg[step];

    int t = blockIdx.x * 256 + threadIdx.x;
    int g = t >> 3;                 // edge index
    int j = t & 7;                  // octet lane
    bool valid = (g < E);
    if (g >= E) g = E - 1;          // clamp; keep lanes converged for shfl

    int w = threadIdx.x & 31;
    int ob = w & 24;                // octet base within warp
    int h = j & 1;                  // o-half
    int fi = j >> 1;                // f offset within each 4-block

    int s = __ldg(ei + g);

    const uint4* __restrict__ Ur = (const uint4*)(U + (long)s * UROWP);
    const float* __restrict__ ear = eat + (long)g * 16;

    // cooperative ea fetch: lane j holds ea[2j], ea[2j+1]
    float2 eap = __ldg((const float2*)ear + j);
    // redistribute: eaf[c] = ea[4c+fi]; src lane = ob + 2c + (fi>>1), comp = fi&1
    float eaf[4];
    int comp = fi & 1;
    int sbase = ob + (fi >> 1);
#pragma unroll
    for (int c = 0; c < 4; ++c) {
        float lo = __shfl_sync(0xffffffffu, eap.x, sbase + 2 * c);
        float hi = __shfl_sync(0xffffffffu, eap.y, sbase + 2 * c);
        eaf[c] = comp ? hi : lo;
    }

    float acc[8];
    if (j < 2) {                    // bias block (f=16), once per o-half group
        uint4 u = __ldg(Ur + 32 + j);
        const __half2* hh = (const __half2*)&u;
#pragma unroll
        for (int k = 0; k < 4; ++k) {
            float2 f2 = __half22float2(hh[k]);
            acc[2 * k + 0] = f2.x;
            acc[2 * k + 1] = f2.y;
        }
    } else {
#pragma unroll
        for (int k = 0; k < 8; ++k) acc[k] = 0.0f;
    }

#pragma unroll
    for (int c = 0; c < 4; ++c) {
        uint4 u = __ldg(Ur + c * 8 + j);    // full 128B line per octet
        float er = eaf[c];
        const __half2* hh = (const __half2*)&u;
#pragma unroll
        for (int k = 0; k < 4; ++k) {
            float2 f2 = __half22float2(hh[k]);
            acc[2 * k + 0] += er * f2.x;
            acc[2 * k + 1] += er * f2.y;
        }
    }

#pragma unroll
    for (int k = 0; k < 8; ++k)
        acc[k] += __shfl_xor_sync(0xffffffffu, acc[k], 2);
#pragma unroll
    for (int k = 0; k < 8; ++k)
        acc[k] += __shfl_xor_sync(0xffffffffu, acc[k], 4);

    if (valid && j < 2) {
        int d = __ldg(ei + E + g);
        float* base = &agg[d * 16 + 8 * h];
        red4(base,     acc[0], acc[1], acc[2], acc[3]);
        red4(base + 4, acc[4], acc[5], acc[6], acc[7]);
    }
}

// ---------------------------------------------------------------------------
// final: 2 lanes per node; lane l computes outputs 16l..16l+15
// ---------------------------------------------------------------------------
__global__ __launch_bounds__(256) void final_kernel(
    const float* __restrict__ w_lin,
    const float* __restrict__ b_lin,
    float* __restrict__ out, int N) {
    __shared__ __align__(16) float wl[32 * 32];
    __shared__ float bl[32];
    for (int k = threadIdx.x; k < 1024; k += 256) wl[k] = w_lin[k];
    if (threadIdx.x < 32) bl[threadIdx.x] = b_lin[threadIdx.x];
    __syncthreads();

    int t = blockIdx.x * 256 + threadIdx.x;
    int n = t >> 1;
    int l = t & 1;
    if (n >= N) return;

    float s[32];
    {
        const float4* ga = (const float4*)(&g_agg[0][n * 16]);
        const float4* gb = (const float4*)(&g_agg[1][n * 16]);
#pragma unroll
        for (int j = 0; j < 4; ++j) {
            float4 va = ga[j];
            s[4 * j + 0] = sigmoidf(va.x); s[4 * j + 1] = sigmoidf(va.y);
            s[4 * j + 2] = sigmoidf(va.z); s[4 * j + 3] = sigmoidf(va.w);
        }
#pragma unroll
        for (int j = 0; j < 4; ++j) {
            float4 vb = gb[j];
            s[16 + 4 * j + 0] = sigmoidf(vb.x); s[16 + 4 * j + 1] = sigmoidf(vb.y);
            s[16 + 4 * j + 2] = sigmoidf(vb.z); s[16 + 4 * j + 3] = sigmoidf(vb.w);
        }
    }

    float4 acc[4];
#pragma unroll
    for (int j = 0; j < 4; ++j) {
        int o = 16 * l + 4 * j;
        acc[j] = make_float4(bl[o], bl[o + 1], bl[o + 2], bl[o + 3]);
    }
#pragma unroll
    for (int k = 0; k < 32; ++k) {
        float sk = s[k];
        const float4* w4 = (const float4*)(wl + k * 32 + 16 * l);
#pragma unroll
        for (int j = 0; j < 4; ++j) {
            float4 w = w4[j];
            acc[j].x += sk * w.x;
            acc[j].y += sk * w.y;
            acc[j].z += sk * w.z;
            acc[j].w += sk * w.w;
        }
    }

    float4* o4 = (float4*)(out + n * 32 + 16 * l);
#pragma unroll
    for (int j = 0; j < 4; ++j)
        o4[j] = make_float4(sigmoidf(acc[j].x), sigmoidf(acc[j].y),
                            sigmoidf(acc[j].z), sigmoidf(acc[j].w));
}

// ---------------------------------------------------------------------------
extern "C" void kernel_launch(void* const* d_in, const int* in_sizes, int n_in,
                              void* d_out, int out_size) {
    const float* x_indivi = (const float*)d_in[0];
    const float* x_src_a  = (const float*)d_in[1];
    const float* x_src_b  = (const float*)d_in[2];
    const int*   ei_a     = (const int*)d_in[3];
    const int*   ei_b     = (const int*)d_in[4];
    const float* ea_a     = (const float*)d_in[5];
    const float* ea_b     = (const float*)d_in[6];
    const float* wm_a     = (const float*)d_in[7];
    const float* bm_a     = (const float*)d_in[8];
    const float* root_a   = (const float*)d_in[9];
    const float* bias_a   = (const float*)d_in[10];
    const float* wm_b     = (const float*)d_in[11];
    const float* bm_b     = (const float*)d_in[12];
    const float* root_b   = (const float*)d_in[13];
    const float* bias_b   = (const float*)d_in[14];
    const float* w_lin    = (const float*)d_in[15];
    const float* b_lin    = (const float*)d_in[16];
    float* out = (float*)d_out;

    int N = in_sizes[0] / 16;
    int E = in_sizes[3] / 2;   // edge_index is [2, E]

    int nb2 = (2 * N + 255) / 256;                 // role 0 blocks
    int nblk_u = (N + 255) / 256;                  // roles 1/2 blocks (N threads)
    int eb8 = (int)(((long)8 * E + 255) / 256);

    // launch 1: prep (init + both U tables)
    prep_kernel<<<dim3(nb2, 3), 256>>>(x_indivi, x_src_a, x_src_b,
                                       root_a, bias_a, root_b, bias_b,
                                       wm_a, bm_a, wm_b, bm_b, N, nblk_u);
    // launch 2: both edge steps
    edge_kernel<<<dim3(eb8, 2), 256>>>(ei_a, ei_b, ea_a, ea_b, E);
    // launch 3: final
    final_kernel<<<nb2, 256>>>(w_lin, b_lin, out, N);
}